// round 2
// baseline (speedup 1.0000x reference)
#include <cuda_runtime.h>

// Scratch (device globals -- no allocation allowed)
__device__ float g_pooled[16*256*25];   // [b][cs][s]
__device__ float g_dots[1281];          // [0:1024) Wq^T bk, [1024:1280) Wk^T bq, [1280] bq.bk
__device__ float g_wqk[1024*256];       // Wq^T Wk  [cr][cs]
__device__ float g_kq[16*1024*25];      // [b][cr][s]  (includes +Wq^T bk)
__device__ float g_v[16*1024*25];       // [b][cr][s]  (includes +bv)
__device__ float g_bqk[400];            // [b][s]

// ---------------------------------------------------------------------------
// Kernel 1: pooled[b,c,s] = mean_w x_skel[b,c,s,w]
// ---------------------------------------------------------------------------
__global__ void k_pool(const float* __restrict__ xs) {
    int o = blockIdx.x * 256 + threadIdx.x;
    if (o < 16*256*25) {
        const float* p = xs + (size_t)o * 25;
        float s = 0.f;
        #pragma unroll
        for (int w = 0; w < 25; w++) s += p[w];
        g_pooled[o] = s * (1.0f / 25.0f);
    }
}

// ---------------------------------------------------------------------------
// Kernel 2: bias folds
// ---------------------------------------------------------------------------
__global__ void k_dots(const float* __restrict__ Wq, const float* __restrict__ bk,
                       const float* __restrict__ Wk, const float* __restrict__ bq) {
    int bid = blockIdx.x, tid = threadIdx.x;
    if (bid < 4) {
        int c = bid * 256 + tid;
        float acc = 0.f;
        for (int i = 0; i < 512; i++) acc += Wq[i*1024 + c] * bk[i];
        g_dots[c] = acc;
    } else if (bid == 4) {
        int c = tid;
        float acc = 0.f;
        for (int i = 0; i < 512; i++) acc += Wk[i*256 + c] * bq[i];
        g_dots[1024 + c] = acc;
    } else {
        __shared__ float red[256];
        float acc = 0.f;
        for (int i = tid; i < 512; i += 256) acc += bq[i] * bk[i];
        red[tid] = acc; __syncthreads();
        for (int st = 128; st > 0; st >>= 1) {
            if (tid < st) red[tid] += red[tid + st];
            __syncthreads();
        }
        if (tid == 0) g_dots[1280] = red[0];
    }
}

// ---------------------------------------------------------------------------
// Kernel 3: Wqk[m,n] = sum_i Wq[i,m] * Wk[i,n]   M=1024, N=256, K=512
// Tiles: BM=64, BN=32, BK=16, 128 threads, 4x4 per thread. grid(8,16)
// ---------------------------------------------------------------------------
__global__ __launch_bounds__(128) void k_gemm0(const float* __restrict__ Wq,
                                               const float* __restrict__ Wk) {
    __shared__ float As[16*64];
    __shared__ float Bs[16*32];
    int m0 = blockIdx.y * 64, n0 = blockIdx.x * 32;
    int t = threadIdx.x;
    int tx = t & 7, ty = t >> 3;
    float acc[4][4] = {};
    for (int k0 = 0; k0 < 512; k0 += 16) {
        #pragma unroll
        for (int u = 0; u < 8; u++) {
            int idx = t + u * 128;
            int kk = idx >> 6, mm = idx & 63;
            As[kk*64 + mm] = Wq[(k0+kk)*1024 + m0 + mm];
        }
        #pragma unroll
        for (int u = 0; u < 4; u++) {
            int idx = t + u * 128;
            int kk = idx >> 5, nn = idx & 31;
            Bs[kk*32 + nn] = Wk[(k0+kk)*256 + n0 + nn];
        }
        __syncthreads();
        #pragma unroll
        for (int kk = 0; kk < 16; kk++) {
            float4 a4 = *(const float4*)&As[kk*64 + ty*4];
            float4 b4 = *(const float4*)&Bs[kk*32 + tx*4];
            float av[4] = {a4.x, a4.y, a4.z, a4.w};
            float bvv[4] = {b4.x, b4.y, b4.z, b4.w};
            #pragma unroll
            for (int i = 0; i < 4; i++)
                #pragma unroll
                for (int j = 0; j < 4; j++)
                    acc[i][j] += av[i] * bvv[j];
        }
        __syncthreads();
    }
    #pragma unroll
    for (int i = 0; i < 4; i++) {
        float4 o = make_float4(acc[i][0], acc[i][1], acc[i][2], acc[i][3]);
        *(float4*)&g_wqk[(m0 + ty*4 + i)*256 + n0 + tx*4] = o;
    }
}

// ---------------------------------------------------------------------------
// Kernel 4: [kq; v; bqk] = [Wqk; Wv; wkbq] @ P + bias
// M=2049 (pad 2112), N=400, K=256. BM=64, BN=80, BK=16, 256 thr, 4x5/thread.
// P[k, j] = pooled[b, k, s] with j = b*25+s. grid(5,33)
// ---------------------------------------------------------------------------
__global__ __launch_bounds__(256) void k_gemm1(const float* __restrict__ Wv,
                                               const float* __restrict__ bv) {
    __shared__ float As[16*68];
    __shared__ float Bs[16*80];
    int m0 = blockIdx.y * 64, j0 = blockIdx.x * 80;
    int t = threadIdx.x, tx = t & 15, ty = t >> 4;
    float acc[4][5] = {};
    for (int k0 = 0; k0 < 256; k0 += 16) {
        #pragma unroll
        for (int u = 0; u < 4; u++) {
            int idx = t + u * 256;
            int mm = idx >> 4, kk = idx & 15;
            int m = m0 + mm, kidx = k0 + kk;
            float a;
            if (m < 1024)       a = g_wqk[m*256 + kidx];
            else if (m < 2048)  a = Wv[(m - 1024)*256 + kidx];
            else if (m == 2048) a = g_dots[1024 + kidx];
            else                a = 0.f;
            As[kk*68 + mm] = a;
        }
        #pragma unroll
        for (int u = 0; u < 5; u++) {
            int idx = t + u * 256;
            int kk = idx / 80, jj = idx - kk * 80;
            int j = j0 + jj;
            int b = j / 25, s = j - b * 25;
            Bs[kk*80 + jj] = g_pooled[((b << 8) + k0 + kk)*25 + s];
        }
        __syncthreads();
        #pragma unroll
        for (int kk = 0; kk < 16; kk++) {
            float4 a4 = *(const float4*)&As[kk*68 + ty*4];
            float av[4] = {a4.x, a4.y, a4.z, a4.w};
            float bb[5];
            #pragma unroll
            for (int u = 0; u < 5; u++) bb[u] = Bs[kk*80 + tx*5 + u];
            #pragma unroll
            for (int i = 0; i < 4; i++)
                #pragma unroll
                for (int u = 0; u < 5; u++)
                    acc[i][u] += av[i] * bb[u];
        }
        __syncthreads();
    }
    #pragma unroll
    for (int i = 0; i < 4; i++) {
        int m = m0 + ty*4 + i;
        if (m > 2048) continue;
        #pragma unroll
        for (int u = 0; u < 5; u++) {
            int j = j0 + tx*5 + u;
            int b = j / 25, s = j - b * 25;
            float val = acc[i][u];
            if (m < 1024)      g_kq[((b << 10) + m)*25 + s] = val + g_dots[m];
            else if (m < 2048) g_v[((b << 10) + (m - 1024))*25 + s] = val + bv[m - 1024];
            else               g_bqk[j] = val + g_dots[1280];
        }
    }
}

// ---------------------------------------------------------------------------
// Kernel 5: fused energy -> softmax -> output residual
// grid(13, 16): blockIdx.y = batch, blockIdx.x = 64-pixel tile. 128 threads.
// ---------------------------------------------------------------------------
__global__ __launch_bounds__(128, 4) void k_main(const float* __restrict__ x,
                                                 const float* __restrict__ gamma_p,
                                                 float* __restrict__ out) {
    __shared__ float xs[64*64];        // c-chunk x pixels
    __shared__ float kqs[64*32];       // c-chunk x s(pad 32)
    __shared__ float es[64*29];        // pixel x s
    __shared__ float attn_ts[25*68];   // s x pixel(pad)
    __shared__ float v_ts[25*68];      // s x c(pad)
    __shared__ float bqks[32];

    int b = blockIdx.y;
    int n0 = blockIdx.x * 64;
    int nvalid = 784 - n0; if (nvalid > 64) nvalid = 64;
    int t = threadIdx.x;

    const float* xb = x + (size_t)(b << 10) * 784 + n0;
    const float* kqb = g_kq + (size_t)(b << 10) * 25;

    // -------- Phase 1: energy e[n,s] = sum_c x[c,n]*kq[c,s] --------
    int nq = t & 15, sg = t >> 4;            // 16 pixel-quads x 8 s-quads
    float acc[4][4] = {};
    for (int c0 = 0; c0 < 1024; c0 += 64) {
        #pragma unroll
        for (int u = 0; u < 32; u++) {
            int idx = t + u * 128;
            int cc = idx >> 6, nn = idx & 63;
            xs[idx] = (nn < nvalid) ? xb[(size_t)(c0 + cc)*784 + nn] : 0.f;
        }
        for (int idx = t; idx < 1600; idx += 128) {
            int cc = idx / 25, s = idx - cc * 25;
            kqs[cc*32 + s] = kqb[(c0 + cc)*25 + s];
        }
        for (int idx = t; idx < 64*7; idx += 128) {
            int cc = idx / 7, s = 25 + (idx - cc*7);
            kqs[cc*32 + s] = 0.f;
        }
        __syncthreads();
        #pragma unroll 4
        for (int cc = 0; cc < 64; cc++) {
            float4 x4 = *(const float4*)&xs[cc*64 + nq*4];
            float4 k4 = *(const float4*)&kqs[cc*32 + sg*4];
            float xv[4] = {x4.x, x4.y, x4.z, x4.w};
            float kv[4] = {k4.x, k4.y, k4.z, k4.w};
            #pragma unroll
            for (int i = 0; i < 4; i++)
                #pragma unroll
                for (int r = 0; r < 4; r++)
                    acc[i][r] += xv[i] * kv[r];
        }
        __syncthreads();
    }
    #pragma unroll
    for (int i = 0; i < 4; i++)
        #pragma unroll
        for (int r = 0; r < 4; r++) {
            int s = sg*4 + r;
            if (s < 25) es[(nq*4 + i)*29 + s] = acc[i][r];
        }
    if (t < 25) bqks[t] = g_bqk[b*25 + t];
    __syncthreads();

    // -------- Phase 2: softmax over s=25 per pixel --------
    if (t < 64) {
        float vals[25];
        float mx = -1e30f;
        #pragma unroll
        for (int s = 0; s < 25; s++) {
            vals[s] = es[t*29 + s] + bqks[s];
            mx = fmaxf(mx, vals[s]);
        }
        float sum = 0.f;
        #pragma unroll
        for (int s = 0; s < 25; s++) {
            float e = __expf(vals[s] - mx);
            vals[s] = e;
            sum += e;
        }
        float inv = 1.f / sum;
        #pragma unroll
        for (int s = 0; s < 25; s++) attn_ts[s*68 + t] = vals[s] * inv;
    }
    __syncthreads();

    // -------- Phase 3: out[c,n] = x[c,n] + gamma * sum_s v[c,s]*attn[n,s] ----
    float gamma = gamma_p[0];
    int cq = t >> 3, ng = t & 7;             // 16 c-quads x 8 n-octets
    bool full = (nvalid == 64);
    for (int c0 = 0; c0 < 1024; c0 += 64) {
        for (int idx = t; idx < 1600; idx += 128) {
            int cc = idx / 25, s = idx - cc * 25;
            v_ts[s*68 + cc] = g_v[((b << 10) + c0 + cc)*25 + s];
        }
        __syncthreads();
        float oacc[4][8] = {};
        #pragma unroll
        for (int s = 0; s < 25; s++) {
            float4 v4 = *(const float4*)&v_ts[s*68 + cq*4];
            float4 a0 = *(const float4*)&attn_ts[s*68 + ng*8];
            float4 a1 = *(const float4*)&attn_ts[s*68 + ng*8 + 4];
            float vv[4] = {v4.x, v4.y, v4.z, v4.w};
            float aa[8] = {a0.x, a0.y, a0.z, a0.w, a1.x, a1.y, a1.z, a1.w};
            #pragma unroll
            for (int i = 0; i < 4; i++)
                #pragma unroll
                for (int j = 0; j < 8; j++)
                    oacc[i][j] += vv[i] * aa[j];
        }
        #pragma unroll
        for (int i = 0; i < 4; i++) {
            int c = c0 + cq*4 + i;
            const float* xr = xb + (size_t)c * 784 + ng*8;
            float* orow = out + ((size_t)(b << 10) + c)*784 + n0 + ng*8;
            if (full) {
                float4 xa = *(const float4*)xr;
                float4 xc = *(const float4*)(xr + 4);
                float4 o0 = make_float4(fmaf(gamma, oacc[i][0], xa.x),
                                        fmaf(gamma, oacc[i][1], xa.y),
                                        fmaf(gamma, oacc[i][2], xa.z),
                                        fmaf(gamma, oacc[i][3], xa.w));
                float4 o1 = make_float4(fmaf(gamma, oacc[i][4], xc.x),
                                        fmaf(gamma, oacc[i][5], xc.y),
                                        fmaf(gamma, oacc[i][6], xc.z),
                                        fmaf(gamma, oacc[i][7], xc.w));
                *(float4*)orow = o0;
                *(float4*)(orow + 4) = o1;
            } else {
                #pragma unroll
                for (int jj = 0; jj < 8; jj++) {
                    int nn = ng*8 + jj;
                    if (nn < nvalid) orow[jj] = fmaf(gamma, oacc[i][jj], xr[jj]);
                }
            }
        }
        __syncthreads();
    }
}

// ---------------------------------------------------------------------------
extern "C" void kernel_launch(void* const* d_in, const int* in_sizes, int n_in,
                              void* d_out, int out_size) {
    const float* x_rgb  = (const float*)d_in[0];
    const float* x_skel = (const float*)d_in[1];
    const float* Wq     = (const float*)d_in[2];
    const float* bq     = (const float*)d_in[3];
    const float* Wk     = (const float*)d_in[4];
    const float* bk     = (const float*)d_in[5];
    const float* Wv     = (const float*)d_in[6];
    const float* bv     = (const float*)d_in[7];
    const float* gamma  = (const float*)d_in[8];
    float* out = (float*)d_out;

    k_pool<<<400, 256>>>(x_skel);
    k_dots<<<6, 256>>>(Wq, bk, Wk, bq);
    k_gemm0<<<dim3(8, 16), 128>>>(Wq, Wk);
    k_gemm1<<<dim3(5, 33), 256>>>(Wv, bv);
    k_main<<<dim3(13, 16), 128>>>(x_rgb, gamma, out);
}

// round 3
// speedup vs baseline: 1.4138x; 1.4138x over previous
#include <cuda_runtime.h>

// ---------------- scratch (device globals; zero-initialized at load) -------
__device__ float g_pooled[16*256*25];      // [b][cs][s]
__device__ float g_dots[1281];             // Wq^T bk | Wk^T bq | bq.bk
__device__ float g_wqk[1024*256];          // Wq^T Wk  [cr][cs]
__device__ float g_kq[16*1024*32];         // [b][cr][32] (pad; pads stay 0-ish)
__device__ float g_v[16*1024*32];          // [b][cr][32]
__device__ float g_bqk[16*32];             // [b][32]
__device__ float g_epart[4*16*784*32];     // [csplit][b][n][32]
__device__ float g_attn[16*784*32];        // [b][n][32] (pads written 0)

// ---------------- packed f32x2 helpers --------------------------------------
__device__ __forceinline__ unsigned long long pack2(float lo, float hi) {
    unsigned long long r;
    asm("mov.b64 %0, {%1,%2};" : "=l"(r) : "f"(lo), "f"(hi));
    return r;
}
__device__ __forceinline__ float2 unpack2(unsigned long long v) {
    float2 r;
    asm("mov.b64 {%0,%1}, %2;" : "=f"(r.x), "=f"(r.y) : "l"(v));
    return r;
}
__device__ __forceinline__ void fma2(unsigned long long& d,
                                     unsigned long long a,
                                     unsigned long long b) {
    asm("fma.rn.f32x2 %0, %1, %2, %0;" : "+l"(d) : "l"(a), "l"(b));
}

// ---------------------------------------------------------------------------
// Kernel 1: pooled[b,c,s] = mean_w x_skel[b,c,s,w]
// ---------------------------------------------------------------------------
__global__ void k_pool(const float* __restrict__ xs) {
    int o = blockIdx.x * 256 + threadIdx.x;
    if (o < 16*256*25) {
        const float* p = xs + (size_t)o * 25;
        float s = 0.f;
        #pragma unroll
        for (int w = 0; w < 25; w++) s += p[w];
        g_pooled[o] = s * (1.0f / 25.0f);
    }
}

// ---------------------------------------------------------------------------
// Kernel 2: bias folds
// ---------------------------------------------------------------------------
__global__ void k_dots(const float* __restrict__ Wq, const float* __restrict__ bk,
                       const float* __restrict__ Wk, const float* __restrict__ bq) {
    int bid = blockIdx.x, tid = threadIdx.x;
    if (bid < 4) {
        int c = bid * 256 + tid;
        float acc = 0.f;
        for (int i = 0; i < 512; i++) acc += Wq[i*1024 + c] * bk[i];
        g_dots[c] = acc;
    } else if (bid == 4) {
        int c = tid;
        float acc = 0.f;
        for (int i = 0; i < 512; i++) acc += Wk[i*256 + c] * bq[i];
        g_dots[1024 + c] = acc;
    } else {
        __shared__ float red[256];
        float acc = 0.f;
        for (int i = tid; i < 512; i += 256) acc += bq[i] * bk[i];
        red[tid] = acc; __syncthreads();
        for (int st = 128; st > 0; st >>= 1) {
            if (tid < st) red[tid] += red[tid + st];
            __syncthreads();
        }
        if (tid == 0) g_dots[1280] = red[0];
    }
}

// ---------------------------------------------------------------------------
// Kernel 3: Wqk[m,n] = sum_i Wq[i,m]*Wk[i,n]  M=1024,N=256,K=512
// BM=64, BN=32, BK=16, 128 thr, thread tile 4m x 4n via f32x2. grid(8,16)
// ---------------------------------------------------------------------------
__global__ __launch_bounds__(128) void k_gemm0(const float* __restrict__ Wq,
                                               const float* __restrict__ Wk) {
    __shared__ float As[16*64];
    __shared__ float Bs[16*32];
    int m0 = blockIdx.y * 64, n0 = blockIdx.x * 32;
    int t = threadIdx.x;
    int tx = t & 7, ty = t >> 3;
    unsigned long long acc2[4][2] = {};
    for (int k0 = 0; k0 < 512; k0 += 16) {
        #pragma unroll
        for (int u = 0; u < 8; u++) {
            int idx = t + u * 128;
            int kk = idx >> 6, mm = idx & 63;
            As[kk*64 + mm] = Wq[(k0+kk)*1024 + m0 + mm];
        }
        #pragma unroll
        for (int u = 0; u < 4; u++) {
            int idx = t + u * 128;
            int kk = idx >> 5, nn = idx & 31;
            Bs[kk*32 + nn] = Wk[(k0+kk)*256 + n0 + nn];
        }
        __syncthreads();
        #pragma unroll
        for (int kk = 0; kk < 16; kk++) {
            float4 a4 = *(const float4*)&As[kk*64 + ty*4];
            ulonglong2 b2 = *(const ulonglong2*)&Bs[kk*32 + tx*4];
            unsigned long long pa[4] = {pack2(a4.x,a4.x), pack2(a4.y,a4.y),
                                        pack2(a4.z,a4.z), pack2(a4.w,a4.w)};
            #pragma unroll
            for (int i = 0; i < 4; i++) {
                fma2(acc2[i][0], pa[i], b2.x);
                fma2(acc2[i][1], pa[i], b2.y);
            }
        }
        __syncthreads();
    }
    #pragma unroll
    for (int i = 0; i < 4; i++) {
        float2 p0 = unpack2(acc2[i][0]), p1 = unpack2(acc2[i][1]);
        float4 o = make_float4(p0.x, p0.y, p1.x, p1.y);
        *(float4*)&g_wqk[(m0 + ty*4 + i)*256 + n0 + tx*4] = o;
    }
}

// ---------------------------------------------------------------------------
// Kernel 4: [kq; v; bqk](b) = [Wqk; Wv; wkbq] @ pooled_b + bias
// grid(33 m-tiles, 16 b). BM=64, S=25(pad 32), BK=32, 128 thr, 4m x 4s f32x2.
// ---------------------------------------------------------------------------
__global__ __launch_bounds__(128) void k_gemm1(const float* __restrict__ Wv,
                                               const float* __restrict__ bv) {
    __shared__ float As[32*68];
    __shared__ float Bs[32*32];
    int m0 = blockIdx.x * 64;
    int b  = blockIdx.y;
    int t = threadIdx.x;
    int tm = t >> 1, th = t & 1;           // A-load mapping
    int tx = t & 7, ty = t >> 3;           // compute mapping
    unsigned long long acc2[4][2] = {};
    for (int k0 = 0; k0 < 256; k0 += 32) {
        // A tile: rows m0..m0+63 of stacked [Wqk(1024); Wv(1024); wkbq(1)]
        int m = m0 + tm;
        #pragma unroll
        for (int u = 0; u < 4; u++) {
            int koff = th*16 + u*4;
            float4 a4;
            if (m < 1024)       a4 = *(const float4*)&g_wqk[m*256 + k0 + koff];
            else if (m < 2048)  a4 = *(const float4*)&Wv[(m-1024)*256 + k0 + koff];
            else if (m == 2048) a4 = *(const float4*)&g_dots[1024 + k0 + koff];
            else                a4 = make_float4(0.f,0.f,0.f,0.f);
            As[(koff+0)*68 + tm] = a4.x;
            As[(koff+1)*68 + tm] = a4.y;
            As[(koff+2)*68 + tm] = a4.z;
            As[(koff+3)*68 + tm] = a4.w;
        }
        // B tile: pooled[b][k0+kk][s], s padded to 32 with zeros
        #pragma unroll
        for (int u = 0; u < 8; u++) {
            int idx = t + u * 128;
            int kk = idx >> 5, s = idx & 31;
            Bs[idx] = (s < 25) ? g_pooled[((b << 8) + k0 + kk)*25 + s] : 0.f;
        }
        __syncthreads();
        #pragma unroll
        for (int kk = 0; kk < 32; kk++) {
            float4 a4 = *(const float4*)&As[kk*68 + ty*4];
            ulonglong2 b2 = *(const ulonglong2*)&Bs[kk*32 + tx*4];
            unsigned long long pa[4] = {pack2(a4.x,a4.x), pack2(a4.y,a4.y),
                                        pack2(a4.z,a4.z), pack2(a4.w,a4.w)};
            #pragma unroll
            for (int i = 0; i < 4; i++) {
                fma2(acc2[i][0], pa[i], b2.x);
                fma2(acc2[i][1], pa[i], b2.y);
            }
        }
        __syncthreads();
    }
    int s0 = tx * 4;
    #pragma unroll
    for (int i = 0; i < 4; i++) {
        int m = m0 + ty*4 + i;
        float2 p0 = unpack2(acc2[i][0]), p1 = unpack2(acc2[i][1]);
        if (m < 1024) {
            float d = g_dots[m];
            float4 o = make_float4(p0.x+d, p0.y+d, p1.x+d, p1.y+d);
            *(float4*)&g_kq[((b << 10) + m)*32 + s0] = o;
        } else if (m < 2048) {
            float d = bv[m - 1024];
            float4 o = make_float4(p0.x+d, p0.y+d, p1.x+d, p1.y+d);
            *(float4*)&g_v[((b << 10) + (m - 1024))*32 + s0] = o;
        } else if (m == 2048) {
            float d = g_dots[1280];
            float4 o = make_float4(p0.x+d, p0.y+d, p1.x+d, p1.y+d);
            *(float4*)&g_bqk[b*32 + s0] = o;
        }
    }
}

// ---------------------------------------------------------------------------
// Kernel 5 (energy partial): epart[z,b,n,s] = sum_{c in z-chunk} x[c,n]*kq[c,s]
// grid(13 px-tiles, 16 b, 4 c-splits), 128 thr. Thread tile 4px x 4s (f32x2/s).
// ---------------------------------------------------------------------------
__global__ __launch_bounds__(128) void k_energy(const float* __restrict__ x) {
    __shared__ float xs[64*64];
    __shared__ float kqs[64*32];
    int n0 = blockIdx.x * 64;
    int b  = blockIdx.y;
    int z  = blockIdx.z;
    int c0 = z * 256;
    int nvalid = 784 - n0; if (nvalid > 64) nvalid = 64;
    int t = threadIdx.x;
    int nq = t & 15, sg = t >> 4;
    unsigned long long acc2[4][2] = {};

    for (int cz = 0; cz < 4; cz++) {
        int cbase = c0 + cz * 64;
        #pragma unroll
        for (int u = 0; u < 32; u++) {
            int idx = t + u * 128;
            int cc = idx >> 6, nn = idx & 63;
            xs[idx] = (nn < nvalid)
                      ? x[(size_t)((b << 10) + cbase + cc)*784 + n0 + nn] : 0.f;
        }
        // kq chunk: 64 rows x 32 = 512 contiguous float4
        const float4* kq4 = (const float4*)(g_kq + (size_t)((b << 10) + cbase)*32);
        float4* kqs4 = (float4*)kqs;
        #pragma unroll
        for (int u = 0; u < 4; u++) kqs4[t + u*128] = kq4[t + u*128];
        __syncthreads();
        #pragma unroll 8
        for (int cc = 0; cc < 64; cc++) {
            float4 x4 = *(const float4*)&xs[cc*64 + nq*4];
            ulonglong2 k2 = *(const ulonglong2*)&kqs[cc*32 + sg*4];
            unsigned long long px[4] = {pack2(x4.x,x4.x), pack2(x4.y,x4.y),
                                        pack2(x4.z,x4.z), pack2(x4.w,x4.w)};
            #pragma unroll
            for (int i = 0; i < 4; i++) {
                fma2(acc2[i][0], px[i], k2.x);
                fma2(acc2[i][1], px[i], k2.y);
            }
        }
        __syncthreads();
    }
    float* ep = g_epart + (size_t)(z*16 + b)*784*32;
    #pragma unroll
    for (int i = 0; i < 4; i++) {
        int n = n0 + nq*4 + i;
        if (n < 784) {
            float2 p0 = unpack2(acc2[i][0]), p1 = unpack2(acc2[i][1]);
            float4 o = make_float4(p0.x, p0.y, p1.x, p1.y);
            *(float4*)&ep[n*32 + sg*4] = o;
        }
    }
}

// ---------------------------------------------------------------------------
// Kernel 6 (softmax): attn[b,n,s] = softmax_s( sum_z epart + bqk ), pads -> 0
// grid(7, 16), 128 thr, one pixel row per thread.
// ---------------------------------------------------------------------------
__global__ __launch_bounds__(128) void k_softmax() {
    __shared__ float bq_s[32];
    int b = blockIdx.y;
    int t = threadIdx.x;
    int n = blockIdx.x * 128 + t;
    if (t < 32) bq_s[t] = (t < 25) ? g_bqk[b*32 + t] : 0.f;
    __syncthreads();
    if (n >= 784) return;

    const size_t part = (size_t)16*784*32;
    const float4* p0 = (const float4*)(g_epart + ((size_t)b*784 + n)*32);
    const float4* p1 = (const float4*)((const float*)p0 + part);
    const float4* p2 = (const float4*)((const float*)p1 + part);
    const float4* p3 = (const float4*)((const float*)p2 + part);
    float e[32];
    #pragma unroll
    for (int j = 0; j < 8; j++) {
        float4 a = p0[j], bb = p1[j], c = p2[j], d = p3[j];
        e[4*j+0] = a.x + bb.x + c.x + d.x;
        e[4*j+1] = a.y + bb.y + c.y + d.y;
        e[4*j+2] = a.z + bb.z + c.z + d.z;
        e[4*j+3] = a.w + bb.w + c.w + d.w;
    }
    float mx = -1e30f;
    #pragma unroll
    for (int s = 0; s < 25; s++) { e[s] += bq_s[s]; mx = fmaxf(mx, e[s]); }
    float sum = 0.f;
    #pragma unroll
    for (int s = 0; s < 25; s++) { e[s] = __expf(e[s] - mx); sum += e[s]; }
    float inv = 1.f / sum;
    #pragma unroll
    for (int s = 0; s < 25; s++) e[s] *= inv;
    #pragma unroll
    for (int s = 25; s < 32; s++) e[s] = 0.f;
    float4* ao = (float4*)(g_attn + ((size_t)b*784 + n)*32);
    #pragma unroll
    for (int j = 0; j < 8; j++)
        ao[j] = make_float4(e[4*j], e[4*j+1], e[4*j+2], e[4*j+3]);
}

// ---------------------------------------------------------------------------
// Kernel 7 (output): out[c,n] = x[c,n] + gamma * sum_s v[c,s]*attn[n,s]
// grid(13 px-tiles, 16 c-tiles, 16 b), 128 thr. Thread tile 4c x 8px (f32x2/px).
// ---------------------------------------------------------------------------
__global__ __launch_bounds__(128) void k_out(const float* __restrict__ x,
                                             const float* __restrict__ gamma_p,
                                             float* __restrict__ out) {
    __shared__ float attn_ts[25*68];
    __shared__ float v_ts[25*68];
    int n0 = blockIdx.x * 64;
    int c0 = blockIdx.y * 64;
    int b  = blockIdx.z;
    int t = threadIdx.x;
    bool full = (n0 + 64 <= 784);

    // transpose-load attn tile [s][px]
    const float4* at4 = (const float4*)(g_attn + (size_t)b*784*32);
    #pragma unroll
    for (int u = 0; u < 4; u++) {
        int idx = t + u*128;
        int row = idx >> 3, q = idx & 7;
        float4 a4 = (n0 + row < 784) ? at4[(n0 + row)*8 + q]
                                     : make_float4(0.f,0.f,0.f,0.f);
        int s = q*4;
        if (s   < 25) attn_ts[(s  )*68 + row] = a4.x;
        if (s+1 < 25) attn_ts[(s+1)*68 + row] = a4.y;
        if (s+2 < 25) attn_ts[(s+2)*68 + row] = a4.z;
        if (s+3 < 25) attn_ts[(s+3)*68 + row] = a4.w;
    }
    // transpose-load v tile [s][c]
    const float4* v4p = (const float4*)(g_v + (size_t)((b << 10) + c0)*32);
    #pragma unroll
    for (int u = 0; u < 4; u++) {
        int idx = t + u*128;
        int row = idx >> 3, q = idx & 7;
        float4 a4 = v4p[row*8 + q];
        int s = q*4;
        if (s   < 25) v_ts[(s  )*68 + row] = a4.x;
        if (s+1 < 25) v_ts[(s+1)*68 + row] = a4.y;
        if (s+2 < 25) v_ts[(s+2)*68 + row] = a4.z;
        if (s+3 < 25) v_ts[(s+3)*68 + row] = a4.w;
    }
    __syncthreads();

    int cq = t >> 3, ng = t & 7;
    unsigned long long acc2[4][4] = {};
    #pragma unroll
    for (int s = 0; s < 25; s++) {
        float4 v4 = *(const float4*)&v_ts[s*68 + cq*4];
        const ulonglong2* ap = (const ulonglong2*)&attn_ts[s*68 + ng*8];
        ulonglong2 A0 = ap[0], A1 = ap[1];
        unsigned long long pv[4] = {pack2(v4.x,v4.x), pack2(v4.y,v4.y),
                                    pack2(v4.z,v4.z), pack2(v4.w,v4.w)};
        #pragma unroll
        for (int i = 0; i < 4; i++) {
            fma2(acc2[i][0], pv[i], A0.x);
            fma2(acc2[i][1], pv[i], A0.y);
            fma2(acc2[i][2], pv[i], A1.x);
            fma2(acc2[i][3], pv[i], A1.y);
        }
    }
    float gamma = gamma_p[0];
    #pragma unroll
    for (int i = 0; i < 4; i++) {
        int c = c0 + cq*4 + i;
        const float* xr = x + (size_t)((b << 10) + c)*784 + n0 + ng*8;
        float* orow = out + (size_t)((b << 10) + c)*784 + n0 + ng*8;
        float2 q0 = unpack2(acc2[i][0]), q1 = unpack2(acc2[i][1]);
        float2 q2 = unpack2(acc2[i][2]), q3 = unpack2(acc2[i][3]);
        if (full) {
            float4 xa = *(const float4*)xr;
            float4 xc = *(const float4*)(xr + 4);
            float4 o0 = make_float4(fmaf(gamma,q0.x,xa.x), fmaf(gamma,q0.y,xa.y),
                                    fmaf(gamma,q1.x,xa.z), fmaf(gamma,q1.y,xa.w));
            float4 o1 = make_float4(fmaf(gamma,q2.x,xc.x), fmaf(gamma,q2.y,xc.y),
                                    fmaf(gamma,q3.x,xc.z), fmaf(gamma,q3.y,xc.w));
            *(float4*)orow = o0;
            *(float4*)(orow + 4) = o1;
        } else {
            float oa[8] = {q0.x,q0.y,q1.x,q1.y,q2.x,q2.y,q3.x,q3.y};
            #pragma unroll
            for (int jj = 0; jj < 8; jj++) {
                int nn = ng*8 + jj;
                if (n0 + nn < 784) orow[jj] = fmaf(gamma, oa[jj], xr[jj]);
            }
        }
    }
}

// ---------------------------------------------------------------------------
extern "C" void kernel_launch(void* const* d_in, const int* in_sizes, int n_in,
                              void* d_out, int out_size) {
    const float* x_rgb  = (const float*)d_in[0];
    const float* x_skel = (const float*)d_in[1];
    const float* Wq     = (const float*)d_in[2];
    const float* bq     = (const float*)d_in[3];
    const float* Wk     = (const float*)d_in[4];
    const float* bk     = (const float*)d_in[5];
    const float* Wv     = (const float*)d_in[6];
    const float* bv     = (const float*)d_in[7];
    const float* gamma  = (const float*)d_in[8];
    float* out = (float*)d_out;

    k_pool   <<<400, 256>>>(x_skel);
    k_dots   <<<6, 256>>>(Wq, bk, Wk, bq);
    k_gemm0  <<<dim3(8, 16), 128>>>(Wq, Wk);
    k_gemm1  <<<dim3(33, 16), 128>>>(Wv, bv);
    k_energy <<<dim3(13, 16, 4), 128>>>(x_rgb);
    k_softmax<<<dim3(7, 16), 128>>>();
    k_out    <<<dim3(13, 16, 16), 128>>>(x_rgb, gamma, out);
}

// round 4
// speedup vs baseline: 1.6998x; 1.2023x over previous
#include <cuda_runtime.h>

// ---------------- scratch (device globals; zero-initialized) ---------------
__device__ float g_pooledp[16*256*32];     // [b][cs][32] padded, pads stay 0
__device__ float g_dots[1281];             // Wq^T bk | Wk^T bq | bq.bk
__device__ float g_wqk[1024*256];          // Wq^T Wk  [cr][cs]
__device__ float g_kq[16*1024*32];         // [b][cr][32]
__device__ float g_v[16*1024*32];          // [b][cr][32]
__device__ float g_bqk[16*32];             // [b][32]
__device__ float g_epart[4*16*784*32];     // [z][b][n][32]
__device__ float g_attn[16*784*32];        // [b][n][32] (pads 0)

// ---------------- packed f32x2 helpers -------------------------------------
__device__ __forceinline__ unsigned long long pack2(float lo, float hi) {
    unsigned long long r;
    asm("mov.b64 %0, {%1,%2};" : "=l"(r) : "f"(lo), "f"(hi));
    return r;
}
__device__ __forceinline__ float2 unpack2(unsigned long long v) {
    float2 r;
    asm("mov.b64 {%0,%1}, %2;" : "=f"(r.x), "=f"(r.y) : "l"(v));
    return r;
}
__device__ __forceinline__ void fma2(unsigned long long& d,
                                     unsigned long long a,
                                     unsigned long long b) {
    asm("fma.rn.f32x2 %0, %1, %2, %0;" : "+l"(d) : "l"(a), "l"(b));
}

// ---------------------------------------------------------------------------
// k_prep: gemm0 (blocks 0..127) | dots (128..138) | pool (139..1738)
// ---------------------------------------------------------------------------
__global__ __launch_bounds__(128) void k_prep(const float* __restrict__ Wq,
                                              const float* __restrict__ bq,
                                              const float* __restrict__ Wk,
                                              const float* __restrict__ bk,
                                              const float* __restrict__ xs_in) {
    __shared__ float sm[1664];   // gemm0: As(1024)+Bs(512); pool: 1600; dots: 128
    int bid = blockIdx.x;
    int t = threadIdx.x;

    if (bid < 128) {
        // ---- gemm0: Wqk[m,n] = sum_i Wq[i,m]*Wk[i,n] ----
        float* As = sm;          // [16][64]
        float* Bs = sm + 1024;   // [16][32]
        int m0 = (bid >> 3) * 64, n0 = (bid & 7) * 32;
        int tx = t & 7, ty = t >> 3;
        unsigned long long acc2[4][2] = {};
        for (int k0 = 0; k0 < 512; k0 += 16) {
            #pragma unroll
            for (int u = 0; u < 8; u++) {
                int idx = t + u * 128;
                int kk = idx >> 6, mm = idx & 63;
                As[kk*64 + mm] = Wq[(k0+kk)*1024 + m0 + mm];
            }
            #pragma unroll
            for (int u = 0; u < 4; u++) {
                int idx = t + u * 128;
                int kk = idx >> 5, nn = idx & 31;
                Bs[kk*32 + nn] = Wk[(k0+kk)*256 + n0 + nn];
            }
            __syncthreads();
            #pragma unroll
            for (int kk = 0; kk < 16; kk++) {
                float4 a4 = *(const float4*)&As[kk*64 + ty*4];
                ulonglong2 b2 = *(const ulonglong2*)&Bs[kk*32 + tx*4];
                unsigned long long pa[4] = {pack2(a4.x,a4.x), pack2(a4.y,a4.y),
                                            pack2(a4.z,a4.z), pack2(a4.w,a4.w)};
                #pragma unroll
                for (int i = 0; i < 4; i++) {
                    fma2(acc2[i][0], pa[i], b2.x);
                    fma2(acc2[i][1], pa[i], b2.y);
                }
            }
            __syncthreads();
        }
        #pragma unroll
        for (int i = 0; i < 4; i++) {
            float2 p0 = unpack2(acc2[i][0]), p1 = unpack2(acc2[i][1]);
            *(float4*)&g_wqk[(m0 + ty*4 + i)*256 + n0 + tx*4] =
                make_float4(p0.x, p0.y, p1.x, p1.y);
        }
    } else if (bid < 136) {
        // ---- dots1: Wq^T bk (1024) ----
        int c = (bid - 128) * 128 + t;
        float acc = 0.f;
        for (int i = 0; i < 512; i++) acc += Wq[i*1024 + c] * bk[i];
        g_dots[c] = acc;
    } else if (bid < 138) {
        // ---- dots2: Wk^T bq (256) ----
        int c = (bid - 136) * 128 + t;
        float acc = 0.f;
        for (int i = 0; i < 512; i++) acc += Wk[i*256 + c] * bq[i];
        g_dots[1024 + c] = acc;
    } else if (bid == 138) {
        // ---- dots3: bq . bk ----
        float acc = 0.f;
        for (int i = t; i < 512; i += 128) acc += bq[i] * bk[i];
        sm[t] = acc; __syncthreads();
        for (int st = 64; st > 0; st >>= 1) {
            if (t < st) sm[t] += sm[t + st];
            __syncthreads();
        }
        if (t == 0) g_dots[1280] = sm[0];
    } else {
        // ---- pool: 64 rows of 25 per block, coalesced load -> smem reduce ----
        int r0 = (bid - 139) * 64;
        const float* src = xs_in + (size_t)r0 * 25;
        for (int i = t; i < 1600; i += 128) sm[i] = src[i];
        __syncthreads();
        if (t < 64) {
            float s = 0.f;
            #pragma unroll
            for (int w = 0; w < 25; w++) s += sm[t*25 + w];
            int o = r0 + t;
            int bc = o / 25, s_idx = o - bc * 25;
            g_pooledp[bc*32 + s_idx] = s * (1.0f / 25.0f);
        }
    }
}

// ---------------------------------------------------------------------------
// k_gemm1: [kq; v; bqk](b) = [Wqk; Wv; wkbq] @ pooledp_b + bias
// grid(17 m-tiles, 16 b), 128 thr. BM=128, S=32, BK=32. thread 8m x 4s f32x2.
// ---------------------------------------------------------------------------
__global__ __launch_bounds__(128) void k_gemm1(const float* __restrict__ Wv,
                                               const float* __restrict__ bv) {
    __shared__ float As[32*132];   // [k][m] padded
    __shared__ float Bs[32*32];    // [k][s]
    int bx = blockIdx.x;
    int b  = blockIdx.y;
    int m0 = bx * 128;
    int t = threadIdx.x;
    int tx = t & 7, ty = t >> 3;
    unsigned long long acc2[8][2] = {};

    const float* arow;
    if (bx < 8)       arow = g_wqk + (size_t)(m0 + t) * 256;
    else if (bx < 16) arow = Wv + (size_t)(m0 - 1024 + t) * 256;
    else              arow = g_dots + 1024;   // only t==0 valid

    for (int k0 = 0; k0 < 256; k0 += 32) {
        // A: each thread loads its m-row's 32 k-values, transposed store
        if (bx < 16 || t == 0) {
            #pragma unroll
            for (int u = 0; u < 8; u++) {
                float4 a4 = *(const float4*)&arow[k0 + u*4];
                As[(u*4+0)*132 + t] = a4.x;
                As[(u*4+1)*132 + t] = a4.y;
                As[(u*4+2)*132 + t] = a4.z;
                As[(u*4+3)*132 + t] = a4.w;
            }
        } else {
            #pragma unroll
            for (int u = 0; u < 32; u++) As[u*132 + t] = 0.f;
        }
        // B: 32k x 32s contiguous from padded pooled
        const float4* bsrc = (const float4*)(g_pooledp + ((b << 8) + k0) * 32);
        float4* bs4 = (float4*)Bs;
        bs4[t] = bsrc[t];
        bs4[t + 128] = bsrc[t + 128];
        __syncthreads();
        #pragma unroll 8
        for (int kk = 0; kk < 32; kk++) {
            float4 alo = *(const float4*)&As[kk*132 + ty*8];
            float4 ahi = *(const float4*)&As[kk*132 + ty*8 + 4];
            ulonglong2 b2 = *(const ulonglong2*)&Bs[kk*32 + tx*4];
            unsigned long long pa[8] = {
                pack2(alo.x,alo.x), pack2(alo.y,alo.y),
                pack2(alo.z,alo.z), pack2(alo.w,alo.w),
                pack2(ahi.x,ahi.x), pack2(ahi.y,ahi.y),
                pack2(ahi.z,ahi.z), pack2(ahi.w,ahi.w)};
            #pragma unroll
            for (int i = 0; i < 8; i++) {
                fma2(acc2[i][0], pa[i], b2.x);
                fma2(acc2[i][1], pa[i], b2.y);
            }
        }
        __syncthreads();
    }
    int s0 = tx * 4;
    #pragma unroll
    for (int i = 0; i < 8; i++) {
        int m = m0 + ty*8 + i;
        float2 p0 = unpack2(acc2[i][0]), p1 = unpack2(acc2[i][1]);
        if (bx < 8) {
            float d = g_dots[m];
            *(float4*)&g_kq[((b << 10) + m)*32 + s0] =
                make_float4(p0.x+d, p0.y+d, p1.x+d, p1.y+d);
        } else if (bx < 16) {
            float d = bv[m - 1024];
            *(float4*)&g_v[((b << 10) + (m - 1024))*32 + s0] =
                make_float4(p0.x+d, p0.y+d, p1.x+d, p1.y+d);
        } else if (m == 2048) {
            float d = g_dots[1280];
            *(float4*)&g_bqk[b*32 + s0] =
                make_float4(p0.x+d, p0.y+d, p1.x+d, p1.y+d);
        }
    }
}

// ---------------------------------------------------------------------------
// k_energy: epart[z,b,n,s] = sum_{c in z-chunk} x[c,n]*kq[c,s]
// grid(7 n-tiles of 112, 16 b, 4 z), 224 thr. thread 4n x 4s.
// ---------------------------------------------------------------------------
__global__ __launch_bounds__(224) void k_energy(const float* __restrict__ x) {
    __shared__ float xs[64*112];
    __shared__ float kqs[64*32];
    int n0 = blockIdx.x * 112;
    int b  = blockIdx.y;
    int z  = blockIdx.z;
    int t = threadIdx.x;
    int nq = t % 28, sg = t / 28;          // 28 n-quads x 8 s-quads
    int lq = t % 28, lc = t / 28;          // load mapping
    unsigned long long acc2[4][2] = {};

    for (int cz = 0; cz < 4; cz++) {
        int cbase = z * 256 + cz * 64;
        const float4* xsrc = (const float4*)x
            + (size_t)((b << 10) + cbase) * 196 + (n0 >> 2);
        #pragma unroll
        for (int u = 0; u < 8; u++) {
            int cc = lc + u * 8;
            *(float4*)&xs[cc*112 + lq*4] = xsrc[(size_t)cc*196 + lq];
        }
        const float4* kq4 = (const float4*)(g_kq + (size_t)((b << 10) + cbase)*32);
        float4* kqs4 = (float4*)kqs;
        kqs4[t] = kq4[t];
        if (t + 224 < 512) kqs4[t + 224] = kq4[t + 224];
        if (t < 512 - 448) kqs4[t + 448] = kq4[t + 448];
        __syncthreads();
        #pragma unroll 8
        for (int cc = 0; cc < 64; cc++) {
            float4 x4 = *(const float4*)&xs[cc*112 + nq*4];
            ulonglong2 k2 = *(const ulonglong2*)&kqs[cc*32 + sg*4];
            unsigned long long px[4] = {pack2(x4.x,x4.x), pack2(x4.y,x4.y),
                                        pack2(x4.z,x4.z), pack2(x4.w,x4.w)};
            #pragma unroll
            for (int i = 0; i < 4; i++) {
                fma2(acc2[i][0], px[i], k2.x);
                fma2(acc2[i][1], px[i], k2.y);
            }
        }
        __syncthreads();
    }
    float* ep = g_epart + (size_t)(z*16 + b)*784*32;
    #pragma unroll
    for (int i = 0; i < 4; i++) {
        int n = n0 + nq*4 + i;
        float2 p0 = unpack2(acc2[i][0]), p1 = unpack2(acc2[i][1]);
        *(float4*)&ep[(size_t)n*32 + sg*4] = make_float4(p0.x, p0.y, p1.x, p1.y);
    }
}

// ---------------------------------------------------------------------------
// k_softmax: attn = softmax_s(sum_z epart + bqk); pads -> 0. grid(7,16), 112 thr.
// ---------------------------------------------------------------------------
__global__ __launch_bounds__(112) void k_softmax() {
    __shared__ float bq_s[32];
    int b = blockIdx.y;
    int t = threadIdx.x;
    int n = blockIdx.x * 112 + t;
    if (t < 32) bq_s[t] = (t < 25) ? g_bqk[b*32 + t] : 0.f;
    __syncthreads();

    const size_t part = (size_t)16*784*32;
    const float4* p0 = (const float4*)(g_epart + ((size_t)b*784 + n)*32);
    const float4* p1 = (const float4*)((const float*)p0 + part);
    const float4* p2 = (const float4*)((const float*)p1 + part);
    const float4* p3 = (const float4*)((const float*)p2 + part);
    float e[32];
    #pragma unroll
    for (int j = 0; j < 8; j++) {
        float4 a = p0[j], bb = p1[j], c = p2[j], d = p3[j];
        e[4*j+0] = a.x + bb.x + c.x + d.x;
        e[4*j+1] = a.y + bb.y + c.y + d.y;
        e[4*j+2] = a.z + bb.z + c.z + d.z;
        e[4*j+3] = a.w + bb.w + c.w + d.w;
    }
    float mx = -1e30f;
    #pragma unroll
    for (int s = 0; s < 25; s++) { e[s] += bq_s[s]; mx = fmaxf(mx, e[s]); }
    float sum = 0.f;
    #pragma unroll
    for (int s = 0; s < 25; s++) { e[s] = __expf(e[s] - mx); sum += e[s]; }
    float inv = 1.f / sum;
    #pragma unroll
    for (int s = 0; s < 25; s++) e[s] *= inv;
    #pragma unroll
    for (int s = 25; s < 32; s++) e[s] = 0.f;
    float4* ao = (float4*)(g_attn + ((size_t)b*784 + n)*32);
    #pragma unroll
    for (int j = 0; j < 8; j++)
        ao[j] = make_float4(e[4*j], e[4*j+1], e[4*j+2], e[4*j+3]);
}

// ---------------------------------------------------------------------------
// k_out: out[c,n] = x[c,n] + gamma * sum_s v[c,s]*attn[n,s]
// grid(7 n-tiles of 112, 16 c-tiles of 64, 16 b), 224 thr. thread 4c x 8n.
// ---------------------------------------------------------------------------
__global__ __launch_bounds__(224) void k_out(const float* __restrict__ x,
                                             const float* __restrict__ gamma_p,
                                             float* __restrict__ out) {
    __shared__ float attn_ts[25*116];   // [s][n]
    __shared__ float v_ts[25*68];       // [s][c]
    int n0 = blockIdx.x * 112;
    int c0 = blockIdx.y * 64;
    int b  = blockIdx.z;
    int t = threadIdx.x;

    // transpose-load attn tile: 112 rows x 8 quads
    const float4* at4 = (const float4*)(g_attn + (size_t)b*784*32);
    #pragma unroll
    for (int u = 0; u < 4; u++) {
        int i = t + u*224;
        int row = i >> 3, q = i & 7;
        float4 a4 = at4[(size_t)(n0 + row)*8 + q];
        int s = q*4;
        if (s   < 25) attn_ts[(s  )*116 + row] = a4.x;
        if (s+1 < 25) attn_ts[(s+1)*116 + row] = a4.y;
        if (s+2 < 25) attn_ts[(s+2)*116 + row] = a4.z;
        if (s+3 < 25) attn_ts[(s+3)*116 + row] = a4.w;
    }
    // transpose-load v tile: 64 rows x 8 quads
    const float4* v4p = (const float4*)(g_v + (size_t)((b << 10) + c0)*32);
    #pragma unroll
    for (int u = 0; u < 3; u++) {
        int i = t + u*224;
        if (i < 512) {
            int row = i >> 3, q = i & 7;
            float4 a4 = v4p[row*8 + q];
            int s = q*4;
            if (s   < 25) v_ts[(s  )*68 + row] = a4.x;
            if (s+1 < 25) v_ts[(s+1)*68 + row] = a4.y;
            if (s+2 < 25) v_ts[(s+2)*68 + row] = a4.z;
            if (s+3 < 25) v_ts[(s+3)*68 + row] = a4.w;
        }
    }
    __syncthreads();

    int ng = t % 14, cq = t / 14;      // 14 n-octets x 16 c-quads
    unsigned long long acc2[4][4] = {};
    #pragma unroll
    for (int s = 0; s < 25; s++) {
        float4 v4 = *(const float4*)&v_ts[s*68 + cq*4];
        const ulonglong2* ap = (const ulonglong2*)&attn_ts[s*116 + ng*8];
        ulonglong2 A0 = ap[0], A1 = ap[1];
        unsigned long long pv[4] = {pack2(v4.x,v4.x), pack2(v4.y,v4.y),
                                    pack2(v4.z,v4.z), pack2(v4.w,v4.w)};
        #pragma unroll
        for (int i = 0; i < 4; i++) {
            fma2(acc2[i][0], pv[i], A0.x);
            fma2(acc2[i][1], pv[i], A0.y);
            fma2(acc2[i][2], pv[i], A1.x);
            fma2(acc2[i][3], pv[i], A1.y);
        }
    }
    float gamma = gamma_p[0];
    #pragma unroll
    for (int i = 0; i < 4; i++) {
        int c = c0 + cq*4 + i;
        size_t off = (size_t)((b << 10) + c)*784 + n0 + ng*8;
        const float* xr = x + off;
        float* orow = out + off;
        float2 q0 = unpack2(acc2[i][0]), q1 = unpack2(acc2[i][1]);
        float2 q2 = unpack2(acc2[i][2]), q3 = unpack2(acc2[i][3]);
        float4 xa = *(const float4*)xr;
        float4 xc = *(const float4*)(xr + 4);
        *(float4*)orow = make_float4(fmaf(gamma,q0.x,xa.x), fmaf(gamma,q0.y,xa.y),
                                     fmaf(gamma,q1.x,xa.z), fmaf(gamma,q1.y,xa.w));
        *(float4*)(orow+4) = make_float4(fmaf(gamma,q2.x,xc.x), fmaf(gamma,q2.y,xc.y),
                                         fmaf(gamma,q3.x,xc.z), fmaf(gamma,q3.y,xc.w));
    }
}

// ---------------------------------------------------------------------------
extern "C" void kernel_launch(void* const* d_in, const int* in_sizes, int n_in,
                              void* d_out, int out_size) {
    const float* x_rgb  = (const float*)d_in[0];
    const float* x_skel = (const float*)d_in[1];
    const float* Wq     = (const float*)d_in[2];
    const float* bq     = (const float*)d_in[3];
    const float* Wk     = (const float*)d_in[4];
    const float* bk     = (const float*)d_in[5];
    const float* Wv     = (const float*)d_in[6];
    const float* bv     = (const float*)d_in[7];
    const float* gamma  = (const float*)d_in[8];
    float* out = (float*)d_out;

    k_prep   <<<1739, 128>>>(Wq, bq, Wk, bk, x_skel);
    k_gemm1  <<<dim3(17, 16), 128>>>(Wv, bv);
    k_energy <<<dim3(7, 16, 4), 224>>>(x_rgb);
    k_softmax<<<dim3(7, 16), 112>>>();
    k_out    <<<dim3(7, 16, 16), 224>>>(x_rgb, gamma, out);
}